// round 16
// baseline (speedup 1.0000x reference)
#include <cuda_runtime.h>
#include <cuda_fp16.h>
#include <mma.h>
#include <math.h>
#include <stdint.h>

using namespace nvcuda;

#define NB 64
#define TT 1024
#define DD 1024
#define HH 1024
#define K4 4096
#define NCTA_REC 128
#define KC 128                      // K-chunk (elements)
#define PE2 136                     // fp16 smem pitch for 128-wide rows (+8 pad)
#define GP 68                       // fp32 staging pitch
#define STAGE_E (96 * PE2)          // elements per stage (A 32 rows + B 64 rows)
#define SBOFF (32 * PE2)            // sB offset within a stage
#define DYN_B (2 * STAGE_E * 2)     // 52224 bytes (two stages)

// ---------------- device globals ----------------
__device__ float g_xW[(size_t)TT * K4 * NB];          // [t][k'][n]
__device__ __half g_WhT16[(size_t)K4 * HH];           // [k'][j]
__device__ __half g_WxT16[(size_t)K4 * DD];           // [k'][d]
__device__ __half g_x16[(size_t)NB * TT * DD];        // [n][t][d]
__device__ __half g_h16[2][(size_t)NB * HH];          // [buf][n][j]
__device__ unsigned int g_bar_count;
__device__ unsigned int g_bar_gen;

__device__ __forceinline__ float sigf(float v) { return 1.0f / (1.0f + __expf(-v)); }
__device__ __forceinline__ float tanhf_fast(float v) {
    float x = fminf(fmaxf(v, -15.0f), 15.0f);
    float e = __expf(2.0f * x);
    return (e - 1.0f) / (e + 1.0f);
}

// ---------------------------------------------------------------------------
// Preps (validated)
// ---------------------------------------------------------------------------
__global__ void xsplit_kernel(const float* __restrict__ x) {
    size_t i = (size_t)blockIdx.x * 256 + threadIdx.x;   // 64M
    g_x16[i] = __float2half(x[i]);
}

// W[j][k] (1024x4096) -> WT16[k'][j], k' = (jout>>3)*32 + gate*8 + (jout&7)
__global__ void wprep_kernel(const float* __restrict__ W, int which) {
    __half* __restrict__ dst = which ? g_WhT16 : g_WxT16;
    const int k0 = blockIdx.x * 32;
    const int j0 = blockIdx.y * 32;
    __shared__ float tile[32][33];
    const int tid = threadIdx.x;
    const int jj = tid >> 5, kk = tid & 31;
    #pragma unroll
    for (int p = 0; p < 4; p++)
        tile[jj + 8 * p][kk] = W[(size_t)(j0 + jj + 8 * p) * K4 + k0 + kk];
    __syncthreads();
    const int r = tid >> 3, j4 = (tid & 7) * 4;
    const int korig = k0 + r;
    const int gate = korig >> 10, jout = korig & 1023;
    const int kp = (jout >> 3) * 32 + gate * 8 + (jout & 7);
    __half h4[4];
    #pragma unroll
    for (int u = 0; u < 4; u++) h4[u] = __float2half(tile[j4 + u][r]);
    *(uint2*)&dst[(size_t)kp * HH + j0 + j4] = *(uint2*)h4;
}

__global__ void init_kernel(const float* __restrict__ h0) {
    int i = blockIdx.x * 256 + threadIdx.x;   // 65536, [n][j]
    g_h16[0][i] = __float2half(h0[i]);
    if (i == 0) { g_bar_count = 0; g_bar_gen = 0; }
}

// ---------------------------------------------------------------------------
// GEMM core: fp16, KC=128, DOUBLE-BUFFERED stages -> 1 bar per chunk.
// CTA tile 32 k' (m) x 64 n; 8 warps = 4 (k-quarter q) x 2 (n-half p);
// warp tile 32x32, 2 ks-steps. q-partials: single-bar 6-slot blob reduction.
// ---------------------------------------------------------------------------
#define ACCX(j) acc[(j) >> 4][((j) >> 3) & 1].x[(j) & 7]

#define WMMA_CHUNK(sA_, sB_)                                                     \
    do {                                                                         \
        _Pragma("unroll")                                                        \
        for (int ks = 0; ks < 2; ks++) {                                         \
            wmma::fragment<wmma::matrix_a, 16, 16, 16, __half, wmma::row_major> fa[2]; \
            wmma::fragment<wmma::matrix_b, 16, 16, 16, __half, wmma::col_major> fb[2]; \
            const int ko_ = q * 32 + ks * 16;                                    \
            _Pragma("unroll")                                                    \
            for (int mi = 0; mi < 2; mi++)                                       \
                wmma::load_matrix_sync(fa[mi], (sA_) + (mi * 16) * PE2 + ko_, PE2); \
            _Pragma("unroll")                                                    \
            for (int ni = 0; ni < 2; ni++)                                       \
                wmma::load_matrix_sync(fb[ni], (sB_) + (p * 32 + ni * 16) * PE2 + ko_, PE2); \
            _Pragma("unroll")                                                    \
            for (int mi = 0; mi < 2; mi++)                                       \
                _Pragma("unroll")                                                \
                for (int ni = 0; ni < 2; ni++)                                   \
                    wmma::mma_sync(acc[mi][ni], fa[mi], fb[ni], acc[mi][ni]);    \
        }                                                                        \
    } while (0)

#define STORE_BLOB(slot_)                                                        \
    do {                                                                         \
        float* bp_ = rsm + (slot_) * 1024 + lane * 4;                            \
        _Pragma("unroll")                                                        \
        for (int e4 = 0; e4 < 8; e4++) {                                         \
            int j_ = e4 * 4;                                                     \
            *(float4*)(bp_ + e4 * 128) =                                         \
                make_float4(ACCX(j_), ACCX(j_ + 1), ACCX(j_ + 2), ACCX(j_ + 3)); \
        }                                                                        \
    } while (0)

#define LOAD_BLOB_ADD(slot_)                                                     \
    do {                                                                         \
        const float* bp_ = rsm + (slot_) * 1024 + lane * 4;                      \
        _Pragma("unroll")                                                        \
        for (int e4 = 0; e4 < 8; e4++) {                                         \
            int j_ = e4 * 4;                                                     \
            float4 v_ = *(const float4*)(bp_ + e4 * 128);                        \
            ACCX(j_) += v_.x; ACCX(j_ + 1) += v_.y;                              \
            ACCX(j_ + 2) += v_.z; ACCX(j_ + 3) += v_.w;                          \
        }                                                                        \
    } while (0)

#define REDUCE_Q()                                                               \
    do {                                                                         \
        if (q > 0) STORE_BLOB((q - 1) * 2 + p);                                  \
        __syncthreads();                                                         \
        if (q == 0) { LOAD_BLOB_ADD(p); LOAD_BLOB_ADD(2 + p); LOAD_BLOB_ADD(4 + p); } \
    } while (0)

// Double-buffered mainloop: bar -> prefetch LDG c+1 -> MMA stage c -> STS stage c+1
#define MAINLOOP_8_DB()                                                          \
    do {                                                                         \
        uint4 rA[2], rB[4];                                                      \
        _Pragma("unroll")                                                        \
        for (int i_ = 0; i_ < 2; i_++) rA[i_] = *(const uint4*)(srcA[i_]);       \
        _Pragma("unroll")                                                        \
        for (int i_ = 0; i_ < 4; i_++) rB[i_] = *(const uint4*)(srcB[i_]);       \
        _Pragma("unroll")                                                        \
        for (int i_ = 0; i_ < 2; i_++) *(uint4*)&dtile[sAoff[i_]] = rA[i_];      \
        _Pragma("unroll")                                                        \
        for (int i_ = 0; i_ < 4; i_++) *(uint4*)&dtile[SBOFF + sBoff[i_]] = rB[i_]; \
        for (int c = 0; c < 8; c++) {                                            \
            __syncthreads();                                                     \
            if (c < 7) {                                                         \
                const int o_ = (c + 1) * KC;                                     \
                _Pragma("unroll")                                                \
                for (int i_ = 0; i_ < 2; i_++) rA[i_] = *(const uint4*)(srcA[i_] + o_); \
                _Pragma("unroll")                                                \
                for (int i_ = 0; i_ < 4; i_++) rB[i_] = *(const uint4*)(srcB[i_] + o_); \
            }                                                                    \
            __half* sAc_ = dtile + (c & 1) * STAGE_E;                            \
            WMMA_CHUNK(sAc_, sAc_ + SBOFF);                                      \
            if (c < 7) {                                                         \
                __half* dst_ = dtile + ((c + 1) & 1) * STAGE_E;                  \
                _Pragma("unroll")                                                \
                for (int i_ = 0; i_ < 2; i_++) *(uint4*)&dst_[sAoff[i_]] = rA[i_]; \
                _Pragma("unroll")                                                \
                for (int i_ = 0; i_ < 4; i_++) *(uint4*)&dst_[SBOFF + sBoff[i_]] = rB[i_]; \
            }                                                                    \
        }                                                                        \
    } while (0)

// ---------------------------------------------------------------------------
// Phase 1: g_xW[t][k'][n] = x @ Wx + b
// ---------------------------------------------------------------------------
__global__ __launch_bounds__(256) void phase1_wmma(const float* __restrict__ b) {
    extern __shared__ __align__(16) __half dtile[];
    __shared__ float rsm[6 * 1024];
    __shared__ float ssm[32 * GP];
    const int tid = threadIdx.x;
    const int w = tid >> 5, lane = tid & 31;
    const int q = w >> 1, p = w & 1;
    const int cta = blockIdx.x;       // k' block (0..127)
    const int t = blockIdx.y;

    int sAoff[2], sBoff[4];
    const __half* srcA[2];
    const __half* srcB[4];
    #pragma unroll
    for (int i = 0; i < 2; i++) {
        const int idx = tid + 256 * i, row = idx >> 4, seg = idx & 15;
        sAoff[i] = row * PE2 + seg * 8;
        srcA[i] = g_WxT16 + (size_t)(cta * 32 + row) * DD + seg * 8;
    }
    #pragma unroll
    for (int i = 0; i < 4; i++) {
        const int idx = tid + 256 * i, row = idx >> 4, seg = idx & 15;
        sBoff[i] = row * PE2 + seg * 8;
        srcB[i] = g_x16 + ((size_t)row * TT + t) * DD + seg * 8;
    }

    wmma::fragment<wmma::accumulator, 16, 16, 16, float> acc[2][2];
    #pragma unroll
    for (int mi = 0; mi < 2; mi++)
        #pragma unroll
        for (int ni = 0; ni < 2; ni++) wmma::fill_fragment(acc[mi][ni], 0.0f);

    MAINLOOP_8_DB();

    REDUCE_Q();
    if (q == 0) {
        #pragma unroll
        for (int mi = 0; mi < 2; mi++)
            #pragma unroll
            for (int ni = 0; ni < 2; ni++)
                wmma::store_matrix_sync(ssm + (mi * 16) * GP + p * 32 + ni * 16,
                                        acc[mi][ni], GP, wmma::mem_row_major);
    }
    __syncthreads();

    float* xwo = g_xW + ((size_t)t * K4 + cta * 32) * 64;
    #pragma unroll
    for (int u = 0; u < 8; u++) {
        const int idx = tid + 256 * u;
        const int lm = idx >> 6, n = idx & 63;
        const int korig = (lm >> 3) * 1024 + cta * 8 + (lm & 7);
        xwo[idx] = ssm[lm * GP + n] + __ldg(&b[korig]);
    }
}

// ---------------------------------------------------------------------------
// Persistent recurrence. 128 CTAs, grid barrier per step.
// Activation is merged into combine (reads raw gsm + xW directly).
// ---------------------------------------------------------------------------
__global__ __launch_bounds__(256, 1) void rec_wmma(float* __restrict__ out) {
    extern __shared__ __align__(16) __half dtile[];
    __shared__ float rsm[6 * 1024];
    __shared__ float gsm[32 * GP];
    __shared__ float csm[8 * GP];
    const int tid = threadIdx.x;
    const int w = tid >> 5, lane = tid & 31;
    const int q = w >> 1, p = w & 1;
    const int cta = blockIdx.x;

    int sAoff[2], sBoff[4];
    const __half* srcA[2];
    size_t boff[4];
    #pragma unroll
    for (int i = 0; i < 2; i++) {
        const int idx = tid + 256 * i, row = idx >> 4, seg = idx & 15;
        sAoff[i] = row * PE2 + seg * 8;
        srcA[i] = g_WhT16 + (size_t)(cta * 32 + row) * HH + seg * 8;
    }
    #pragma unroll
    for (int i = 0; i < 4; i++) {
        const int idx = tid + 256 * i, row = idx >> 4, seg = idx & 15;
        sBoff[i] = row * PE2 + seg * 8;
        boff[i] = (size_t)row * HH + seg * 8;
    }

    for (int i = tid; i < 8 * GP; i += 256) csm[i] = 0.f;
    __syncthreads();

    const int cn = tid >> 2;            // n for combine
    const int jp = (tid & 3) * 2;       // jl pair base

    for (int t = 0; t < TT; t++) {
        const __half* srcB[4];
        #pragma unroll
        for (int i = 0; i < 4; i++) srcB[i] = g_h16[t & 1] + boff[i];

        wmma::fragment<wmma::accumulator, 16, 16, 16, float> acc[2][2];
        #pragma unroll
        for (int mi = 0; mi < 2; mi++)
            #pragma unroll
            for (int ni = 0; ni < 2; ni++) wmma::fill_fragment(acc[mi][ni], 0.0f);

        MAINLOOP_8_DB();

        REDUCE_Q();
        if (q == 0) {
            #pragma unroll
            for (int mi = 0; mi < 2; mi++)
                #pragma unroll
                for (int ni = 0; ni < 2; ni++)
                    wmma::store_matrix_sync(gsm + (mi * 16) * GP + p * 32 + ni * 16,
                                            acc[mi][ni], GP, wmma::mem_row_major);
        }
        __syncthreads();

        // merged activation + combine: thread -> (n = cn, jl in {jp, jp+1})
        const float* xwp = g_xW + ((size_t)t * K4 + cta * 32) * 64;
        float hv[2];
        __half h2[2];
        #pragma unroll
        for (int u = 0; u < 2; u++) {
            const int jl = jp + u;
            const float iv = sigf(gsm[(jl)      * GP + cn] + __ldg(&xwp[(jl)      * 64 + cn]));
            const float fv = sigf(gsm[(8 + jl)  * GP + cn] + __ldg(&xwp[(8 + jl)  * 64 + cn]));
            const float ov = sigf(gsm[(16 + jl) * GP + cn] + __ldg(&xwp[(16 + jl) * 64 + cn]));
            const float gv = tanhf_fast(gsm[(24 + jl) * GP + cn] + __ldg(&xwp[(24 + jl) * 64 + cn]));
            const float cprev = csm[jl * GP + cn];
            const float cnew = fv * cprev + iv * gv;
            csm[jl * GP + cn] = cnew;
            const float h = ov * tanhf_fast(cnew);
            hv[u] = h;
            h2[u] = __float2half(h);
        }
        *(float2*)&out[((size_t)cn * TT + t) * HH + cta * 8 + jp] = make_float2(hv[0], hv[1]);
        const int nb = (t + 1) & 1;
        *(uint32_t*)&g_h16[nb][(size_t)cn * HH + cta * 8 + jp] = *(uint32_t*)h2;

        // grid barrier (128 CTAs, 1/SM, co-resident)
        __syncthreads();
        if (tid == 0) {
            __threadfence();
            unsigned int ticket = atomicAdd(&g_bar_count, 1);
            if (ticket == NCTA_REC - 1) {
                g_bar_count = 0;
                __threadfence();
                atomicAdd(&g_bar_gen, 1);
            } else {
                while (*(volatile unsigned int*)&g_bar_gen < (unsigned)(t + 1)) { }
            }
            __threadfence();
        }
        __syncthreads();
    }
}

// ---------------------------------------------------------------------------
extern "C" void kernel_launch(void* const* d_in, const int* in_sizes, int n_in,
                              void* d_out, int out_size)
{
    (void)in_sizes; (void)n_in; (void)out_size;
    const float* x  = (const float*)d_in[0];
    const float* h0 = (const float*)d_in[1];
    const float* Wx = (const float*)d_in[2];
    const float* Wh = (const float*)d_in[3];
    const float* b  = (const float*)d_in[4];
    float* out = (float*)d_out;

    // dynamic-smem opt-in (host attribute set each call; no allocation)
    cudaFuncSetAttribute(phase1_wmma, cudaFuncAttributeMaxDynamicSharedMemorySize, DYN_B);
    cudaFuncSetAttribute(rec_wmma,    cudaFuncAttributeMaxDynamicSharedMemorySize, DYN_B);

    xsplit_kernel<<<262144, 256>>>(x);
    wprep_kernel<<<dim3(128, 32), 256>>>(Wx, 0);   // -> g_WxT16
    wprep_kernel<<<dim3(128, 32), 256>>>(Wh, 1);   // -> g_WhT16
    init_kernel<<<256, 256>>>(h0);
    phase1_wmma<<<dim3(128, 1024), 256, DYN_B>>>(b);
    rec_wmma<<<NCTA_REC, 256, DYN_B>>>(out);
}

// round 17
// speedup vs baseline: 1.3105x; 1.3105x over previous
#include <cuda_runtime.h>
#include <cuda_fp16.h>
#include <mma.h>
#include <math.h>
#include <stdint.h>

using namespace nvcuda;

#define NB 64
#define TT 1024
#define DD 1024
#define HH 1024
#define K4 4096
#define NCTA_REC 128
#define KC 128                      // K-chunk (elements)
#define PE2 136                     // fp16 smem pitch for 128-wide rows (+8 pad)
#define GP 68                       // fp32 staging pitch
#define SB_OFF (32 * PE2)           // phase1: sB offset in dynamic tile
#define DYN_P1 ((32 * PE2 + 64 * PE2) * 2)          // 26112 B (phase1 tile)
#define ACHUNK (32 * PE2)           // rec: one A chunk (32 rows)
#define DYN_REC ((8 * ACHUNK + 64 * PE2) * 2)       // 87040 B (persistent A + B stage)

// ---------------- device globals ----------------
__device__ float g_xW[(size_t)TT * K4 * NB];          // [t][k'][n]
__device__ __half g_WhT16[(size_t)K4 * HH];           // [k'][j]
__device__ __half g_WxT16[(size_t)K4 * DD];           // [k'][d]
__device__ __half g_x16[(size_t)NB * TT * DD];        // [n][t][d]
__device__ __half g_h16[2][(size_t)NB * HH];          // [buf][n][j]
__device__ unsigned int g_bar_count;
__device__ unsigned int g_bar_gen;

__device__ __forceinline__ float sigf(float v) { return 1.0f / (1.0f + __expf(-v)); }
__device__ __forceinline__ float tanhf_fast(float v) {
    float x = fminf(fmaxf(v, -15.0f), 15.0f);
    float e = __expf(2.0f * x);
    return (e - 1.0f) / (e + 1.0f);
}

// ---------------------------------------------------------------------------
// Preps (validated)
// ---------------------------------------------------------------------------
__global__ void xsplit_kernel(const float* __restrict__ x) {
    size_t i = (size_t)blockIdx.x * 256 + threadIdx.x;   // 64M
    g_x16[i] = __float2half(x[i]);
}

// W[j][k] (1024x4096) -> WT16[k'][j], k' = (jout>>3)*32 + gate*8 + (jout&7)
__global__ void wprep_kernel(const float* __restrict__ W, int which) {
    __half* __restrict__ dst = which ? g_WhT16 : g_WxT16;
    const int k0 = blockIdx.x * 32;
    const int j0 = blockIdx.y * 32;
    __shared__ float tile[32][33];
    const int tid = threadIdx.x;
    const int jj = tid >> 5, kk = tid & 31;
    #pragma unroll
    for (int p = 0; p < 4; p++)
        tile[jj + 8 * p][kk] = W[(size_t)(j0 + jj + 8 * p) * K4 + k0 + kk];
    __syncthreads();
    const int r = tid >> 3, j4 = (tid & 7) * 4;
    const int korig = k0 + r;
    const int gate = korig >> 10, jout = korig & 1023;
    const int kp = (jout >> 3) * 32 + gate * 8 + (jout & 7);
    __half h4[4];
    #pragma unroll
    for (int u = 0; u < 4; u++) h4[u] = __float2half(tile[j4 + u][r]);
    *(uint2*)&dst[(size_t)kp * HH + j0 + j4] = *(uint2*)h4;
}

__global__ void init_kernel(const float* __restrict__ h0) {
    int i = blockIdx.x * 256 + threadIdx.x;   // 65536, [n][j]
    g_h16[0][i] = __float2half(h0[i]);
    if (i == 0) { g_bar_count = 0; g_bar_gen = 0; }
}

// ---------------------------------------------------------------------------
// GEMM core: fp16, KC=128 (8 chunks). CTA tile 32 k' (m) x 64 n; 8 warps =
// 4 (k-quarter q) x 2 (n-half p); warp tile 32x32, 2 ks-steps.
// q-partials: single-bar 6-slot blob reduction. (R15 proven structure.)
// ---------------------------------------------------------------------------
#define ACCX(j) acc[(j) >> 4][((j) >> 3) & 1].x[(j) & 7]

#define WMMA_CHUNK(sA_, sB_)                                                     \
    do {                                                                         \
        _Pragma("unroll")                                                        \
        for (int ks = 0; ks < 2; ks++) {                                         \
            wmma::fragment<wmma::matrix_a, 16, 16, 16, __half, wmma::row_major> fa[2]; \
            wmma::fragment<wmma::matrix_b, 16, 16, 16, __half, wmma::col_major> fb[2]; \
            const int ko_ = q * 32 + ks * 16;                                    \
            _Pragma("unroll")                                                    \
            for (int mi = 0; mi < 2; mi++)                                       \
                wmma::load_matrix_sync(fa[mi], (sA_) + (mi * 16) * PE2 + ko_, PE2); \
            _Pragma("unroll")                                                    \
            for (int ni = 0; ni < 2; ni++)                                       \
                wmma::load_matrix_sync(fb[ni], (sB_) + (p * 32 + ni * 16) * PE2 + ko_, PE2); \
            _Pragma("unroll")                                                    \
            for (int mi = 0; mi < 2; mi++)                                       \
                _Pragma("unroll")                                                \
                for (int ni = 0; ni < 2; ni++)                                   \
                    wmma::mma_sync(acc[mi][ni], fa[mi], fb[ni], acc[mi][ni]);    \
        }                                                                        \
    } while (0)

#define STORE_BLOB(slot_)                                                        \
    do {                                                                         \
        float* bp_ = rsm + (slot_) * 1024 + lane * 4;                            \
        _Pragma("unroll")                                                        \
        for (int e4 = 0; e4 < 8; e4++) {                                         \
            int j_ = e4 * 4;                                                     \
            *(float4*)(bp_ + e4 * 128) =                                         \
                make_float4(ACCX(j_), ACCX(j_ + 1), ACCX(j_ + 2), ACCX(j_ + 3)); \
        }                                                                        \
    } while (0)

#define LOAD_BLOB_ADD(slot_)                                                     \
    do {                                                                         \
        const float* bp_ = rsm + (slot_) * 1024 + lane * 4;                      \
        _Pragma("unroll")                                                        \
        for (int e4 = 0; e4 < 8; e4++) {                                         \
            int j_ = e4 * 4;                                                     \
            float4 v_ = *(const float4*)(bp_ + e4 * 128);                        \
            ACCX(j_) += v_.x; ACCX(j_ + 1) += v_.y;                              \
            ACCX(j_ + 2) += v_.z; ACCX(j_ + 3) += v_.w;                          \
        }                                                                        \
    } while (0)

#define REDUCE_Q()                                                               \
    do {                                                                         \
        if (q > 0) STORE_BLOB((q - 1) * 2 + p);                                  \
        __syncthreads();                                                         \
        if (q == 0) { LOAD_BLOB_ADD(p); LOAD_BLOB_ADD(2 + p); LOAD_BLOB_ADD(4 + p); } \
    } while (0)

// ---------------------------------------------------------------------------
// Phase 1: g_xW[t][k'][n] = x @ Wx + b   (exact R15 structure)
// ---------------------------------------------------------------------------
__global__ __launch_bounds__(256) void phase1_wmma(const float* __restrict__ b) {
    extern __shared__ __align__(16) __half dtile[];
    __half* sA = dtile;
    __half* sB = dtile + SB_OFF;
    __shared__ float rsm[6 * 1024];
    __shared__ float ssm[32 * GP];
    const int tid = threadIdx.x;
    const int w = tid >> 5, lane = tid & 31;
    const int q = w >> 1, p = w & 1;
    const int cta = blockIdx.x;       // k' block (0..127)
    const int t = blockIdx.y;

    int sAoff[2], sBoff[4];
    const __half* srcA[2];
    const __half* srcB[4];
    #pragma unroll
    for (int i = 0; i < 2; i++) {
        const int idx = tid + 256 * i, row = idx >> 4, seg = idx & 15;
        sAoff[i] = row * PE2 + seg * 8;
        srcA[i] = g_WxT16 + (size_t)(cta * 32 + row) * DD + seg * 8;
    }
    #pragma unroll
    for (int i = 0; i < 4; i++) {
        const int idx = tid + 256 * i, row = idx >> 4, seg = idx & 15;
        sBoff[i] = row * PE2 + seg * 8;
        srcB[i] = g_x16 + ((size_t)row * TT + t) * DD + seg * 8;
    }

    wmma::fragment<wmma::accumulator, 16, 16, 16, float> acc[2][2];
    #pragma unroll
    for (int mi = 0; mi < 2; mi++)
        #pragma unroll
        for (int ni = 0; ni < 2; ni++) wmma::fill_fragment(acc[mi][ni], 0.0f);

    {
        uint4 rA[2], rB[4];
        #pragma unroll
        for (int i = 0; i < 2; i++) rA[i] = *(const uint4*)(srcA[i]);
        #pragma unroll
        for (int i = 0; i < 4; i++) rB[i] = *(const uint4*)(srcB[i]);
        for (int c = 0; c < 8; c++) {
            __syncthreads();
            #pragma unroll
            for (int i = 0; i < 2; i++) *(uint4*)&sA[sAoff[i]] = rA[i];
            #pragma unroll
            for (int i = 0; i < 4; i++) *(uint4*)&sB[sBoff[i]] = rB[i];
            __syncthreads();
            if (c < 7) {
                const int o = (c + 1) * KC;
                #pragma unroll
                for (int i = 0; i < 2; i++) rA[i] = *(const uint4*)(srcA[i] + o);
                #pragma unroll
                for (int i = 0; i < 4; i++) rB[i] = *(const uint4*)(srcB[i] + o);
            }
            WMMA_CHUNK(sA, sB);
        }
    }

    REDUCE_Q();
    if (q == 0) {
        #pragma unroll
        for (int mi = 0; mi < 2; mi++)
            #pragma unroll
            for (int ni = 0; ni < 2; ni++)
                wmma::store_matrix_sync(ssm + (mi * 16) * GP + p * 32 + ni * 16,
                                        acc[mi][ni], GP, wmma::mem_row_major);
    }
    __syncthreads();

    float* xwo = g_xW + ((size_t)t * K4 + cta * 32) * 64;
    #pragma unroll
    for (int u = 0; u < 8; u++) {
        const int idx = tid + 256 * u;
        const int lm = idx >> 6, n = idx & 63;
        const int korig = (lm >> 3) * 1024 + cta * 8 + (lm & 7);
        xwo[idx] = ssm[lm * GP + n] + __ldg(&b[korig]);
    }
}

// ---------------------------------------------------------------------------
// Persistent recurrence. Wh tile (32 rows x 1024 = all 8 chunks) loaded into
// smem ONCE before the t-loop; mainloop stages only B (h). R15 bar structure.
// ---------------------------------------------------------------------------
__global__ __launch_bounds__(256, 1) void rec_wmma(float* __restrict__ out) {
    extern __shared__ __align__(16) __half dtile[];
    __half* sAper = dtile;                    // [chunk][32][PE2], 8 chunks
    __half* sB = dtile + 8 * ACHUNK;          // one B stage [64][PE2]
    __shared__ float rsm[6 * 1024];
    __shared__ float gsm[32 * GP];
    __shared__ float csm[8 * GP];
    const int tid = threadIdx.x;
    const int w = tid >> 5, lane = tid & 31;
    const int q = w >> 1, p = w & 1;
    const int cta = blockIdx.x;

    int sBoff[4];
    size_t boff[4];
    #pragma unroll
    for (int i = 0; i < 4; i++) {
        const int idx = tid + 256 * i, row = idx >> 4, seg = idx & 15;
        sBoff[i] = row * PE2 + seg * 8;
        boff[i] = (size_t)row * HH + seg * 8;
    }

    // ---- persistent A preload: whole Wh tile, all 8 chunks ----
    #pragma unroll
    for (int i = 0; i < 2; i++) {
        const int idx = tid + 256 * i, row = idx >> 4, seg = idx & 15;
        const __half* src = g_WhT16 + (size_t)(cta * 32 + row) * HH + seg * 8;
        #pragma unroll
        for (int c = 0; c < 8; c++)
            *(uint4*)&sAper[c * ACHUNK + row * PE2 + seg * 8] =
                *(const uint4*)(src + c * KC);
    }
    for (int i = tid; i < 8 * GP; i += 256) csm[i] = 0.f;
    __syncthreads();

    const int cn = tid >> 2;            // n for combine
    const int jp = (tid & 3) * 2;       // jl pair base

    for (int t = 0; t < TT; t++) {
        const __half* hb = g_h16[t & 1];

        const float* xwp = g_xW + ((size_t)t * K4 + cta * 32) * 64;
        float xwr[8];
        #pragma unroll
        for (int u = 0; u < 8; u++) xwr[u] = __ldg(&xwp[tid + 256 * u]);

        wmma::fragment<wmma::accumulator, 16, 16, 16, float> acc[2][2];
        #pragma unroll
        for (int mi = 0; mi < 2; mi++)
            #pragma unroll
            for (int ni = 0; ni < 2; ni++) wmma::fill_fragment(acc[mi][ni], 0.0f);

        // mainloop: B-only staging (R15 bar structure)
        {
            uint4 rB[4];
            #pragma unroll
            for (int i = 0; i < 4; i++) rB[i] = *(const uint4*)(hb + boff[i]);
            for (int c = 0; c < 8; c++) {
                __syncthreads();
                #pragma unroll
                for (int i = 0; i < 4; i++) *(uint4*)&sB[sBoff[i]] = rB[i];
                __syncthreads();
                if (c < 7) {
                    const int o = (c + 1) * KC;
                    #pragma unroll
                    for (int i = 0; i < 4; i++) rB[i] = *(const uint4*)(hb + boff[i] + o);
                }
                WMMA_CHUNK(sAper + c * ACHUNK, sB);
            }
        }

        REDUCE_Q();
        if (q == 0) {
            #pragma unroll
            for (int mi = 0; mi < 2; mi++)
                #pragma unroll
                for (int ni = 0; ni < 2; ni++)
                    wmma::store_matrix_sync(gsm + (mi * 16) * GP + p * 32 + ni * 16,
                                            acc[mi][ni], GP, wmma::mem_row_major);
        }
        __syncthreads();

        // activation: lm = gate*8 + jl; gate 3 (lm>=24) uses tanh
        #pragma unroll
        for (int u = 0; u < 8; u++) {
            const int idx = tid + 256 * u;
            const int lm = idx >> 6, n = idx & 63;
            const float v = gsm[lm * GP + n] + xwr[u];
            gsm[lm * GP + n] = (lm >= 24) ? tanhf_fast(v) : sigf(v);
        }
        __syncthreads();

        // combine: thread -> (n = cn, jl in {jp, jp+1})
        float hv[2];
        __half h2[2];
        #pragma unroll
        for (int u = 0; u < 2; u++) {
            const int jl = jp + u;
            const float iv = gsm[(jl)      * GP + cn];
            const float fv = gsm[(8 + jl)  * GP + cn];
            const float ov = gsm[(16 + jl) * GP + cn];
            const float gv = gsm[(24 + jl) * GP + cn];
            const float cprev = csm[jl * GP + cn];
            const float cnew = fv * cprev + iv * gv;
            csm[jl * GP + cn] = cnew;
            const float h = ov * tanhf_fast(cnew);
            hv[u] = h;
            h2[u] = __float2half(h);
        }
        *(float2*)&out[((size_t)cn * TT + t) * HH + cta * 8 + jp] = make_float2(hv[0], hv[1]);
        const int nb = (t + 1) & 1;
        *(uint32_t*)&g_h16[nb][(size_t)cn * HH + cta * 8 + jp] = *(uint32_t*)h2;

        // grid barrier (128 CTAs, 1/SM, co-resident)
        __syncthreads();
        if (tid == 0) {
            __threadfence();
            unsigned int ticket = atomicAdd(&g_bar_count, 1);
            if (ticket == NCTA_REC - 1) {
                g_bar_count = 0;
                __threadfence();
                atomicAdd(&g_bar_gen, 1);
            } else {
                while (*(volatile unsigned int*)&g_bar_gen < (unsigned)(t + 1)) { }
            }
            __threadfence();
        }
        __syncthreads();
    }
}

// ---------------------------------------------------------------------------
extern "C" void kernel_launch(void* const* d_in, const int* in_sizes, int n_in,
                              void* d_out, int out_size)
{
    (void)in_sizes; (void)n_in; (void)out_size;
    const float* x  = (const float*)d_in[0];
    const float* h0 = (const float*)d_in[1];
    const float* Wx = (const float*)d_in[2];
    const float* Wh = (const float*)d_in[3];
    const float* b  = (const float*)d_in[4];
    float* out = (float*)d_out;

    // dynamic-smem opt-in (host attribute set each call; no allocation)
    cudaFuncSetAttribute(phase1_wmma, cudaFuncAttributeMaxDynamicSharedMemorySize, DYN_P1);
    cudaFuncSetAttribute(rec_wmma,    cudaFuncAttributeMaxDynamicSharedMemorySize, DYN_REC);

    xsplit_kernel<<<262144, 256>>>(x);
    wprep_kernel<<<dim3(128, 32), 256>>>(Wx, 0);   // -> g_WxT16
    wprep_kernel<<<dim3(128, 32), 256>>>(Wh, 1);   // -> g_WhT16
    init_kernel<<<256, 256>>>(h0);
    phase1_wmma<<<dim3(128, 1024), 256, DYN_P1>>>(b);
    rec_wmma<<<NCTA_REC, 256, DYN_REC>>>(out);
}